// round 10
// baseline (speedup 1.0000x reference)
#include <cuda_runtime.h>
#include <stdint.h>
#include <math.h>

#define B_TOTAL  2048
#define N_NEIGH  64
#define IN_DIM   256
#define NH       8
#define HD       32

// Scratch (allocation-free rule: __device__ globals)
__device__ float g_v[IN_DIM * NH];                         // v[in][h]
__device__ float g_s[(size_t)B_TOTAL * NH * IN_DIM];       // s[b][h][in]

__device__ __forceinline__ uint32_t smem_u32(const void* p) {
    uint32_t a;
    asm("{ .reg .u64 t; cvta.to.shared.u64 t, %1; cvt.u32.u64 %0, t; }" : "=r"(a) : "l"(p));
    return a;
}
__device__ __forceinline__ void mbar_wait(uint32_t mbar, uint32_t parity) {
    asm volatile(
        "{\n\t.reg .pred P;\n\t"
        "WAIT_%=:\n\t"
        "mbarrier.try_wait.parity.acquire.cta.shared::cta.b64 P, [%0], %1, 0x989680;\n\t"
        "@!P bra.uni WAIT_%=;\n\t"
        "}" :: "r"(mbar), "r"(parity) : "memory");
}

// ---------------------------------------------------------------------------
// Kernel 0: v[in][h] = sum_d W[in][h*32+d] * W_att[h][d]
// ---------------------------------------------------------------------------
__global__ __launch_bounds__(64, 8)
void k_compute_v(const float* __restrict__ W, const float* __restrict__ Wa, int base) {
    const int idx = base + blockIdx.x * 64 + threadIdx.x;
    const int in  = idx >> 3;
    const int h   = idx & 7;
    const float4* row = reinterpret_cast<const float4*>(W + (size_t)in * (NH * HD) + h * HD);
    const float4* wa4 = reinterpret_cast<const float4*>(Wa) + h * 8;
    float4 w[8];
#pragma unroll
    for (int q = 0; q < 8; q++) w[q] = row[q];
    float acc = 0.f;
#pragma unroll
    for (int q = 0; q < 8; q++) {
        float4 a4 = __ldg(&wa4[q]);
        acc += w[q].x * a4.x + w[q].y * a4.y + w[q].z * a4.z + w[q].w * a4.w;
    }
    g_v[in * NH + h] = acc;
}

// ---------------------------------------------------------------------------
// Stage 1 (v5): hj via ONE cp.async.bulk (64KB) -> smem (off the L1 path),
// split logits: hi-half from registers overlaps the bulk copy.
//   e = leaky( hi.v + hj.v );  alpha = softmax_n(e);  s = alpha^T hj
// smem (floats): hj_s[64][256] @0; e_s[64][8] @16384; alpha_s[64][8] @16896;
//                mbar (u64) @17408
// ---------------------------------------------------------------------------
#define S1_SMEM_BYTES ((16384 + 512 + 512 + 4) * 4)

__global__ __launch_bounds__(256, 3)
void k_stage1(const float* __restrict__ hi, const float* __restrict__ hj, int b_base) {
    extern __shared__ __align__(16) float smem[];
    float* hj_s    = smem;            // [64][256]
    float* e_s     = smem + 16384;    // [64][8]
    float* alpha_s = smem + 16896;    // [64][8]
    unsigned long long* mbar = reinterpret_cast<unsigned long long*>(smem + 17408);

    const int b    = b_base + blockIdx.x;
    const int t    = threadIdx.x;
    const int w    = t >> 5;
    const int lane = t & 31;

    const float4* hib = reinterpret_cast<const float4*>(hi + (size_t)b * N_NEIGH * IN_DIM);
    const float*  hjb = hj + (size_t)b * N_NEIGH * IN_DIM;
    const float4* hjs4 = reinterpret_cast<const float4*>(hj_s);
    const float4* vg  = reinterpret_cast<const float4*>(g_v);

    const uint32_t mb  = smem_u32(mbar);
    const uint32_t dst = smem_u32(hj_s);

    // ---- 1. one 64KB bulk async copy: hj tile -> smem ----
    if (t == 0)
        asm volatile("mbarrier.init.shared.b64 [%0], %1;" :: "r"(mb), "r"(1) : "memory");
    __syncthreads();
    if (t == 0) {
        asm volatile("mbarrier.arrive.expect_tx.shared.b64 _, [%0], %1;"
                     :: "r"(mb), "r"(65536) : "memory");
        asm volatile("cp.async.bulk.shared::cta.global.mbarrier::complete_tx::bytes "
                     "[%0], [%1], %2, [%3];"
                     :: "r"(dst), "l"(hjb), "r"(65536), "r"(mb) : "memory");
    }

    // ---- 2. hi half of logits (registers only; overlaps the copy) ----
#pragma unroll
    for (int pass = 0; pass < 2; pass++) {
        const int co = pass * 32;
        float va[4][8];
#pragma unroll
        for (int j = 0; j < 4; j++) {
            const int ia = 128 * pass + 4 * lane + j;
            float4 p0 = vg[ia * 2], p1 = vg[ia * 2 + 1];
            va[j][0]=p0.x; va[j][1]=p0.y; va[j][2]=p0.z; va[j][3]=p0.w;
            va[j][4]=p1.x; va[j][5]=p1.y; va[j][6]=p1.z; va[j][7]=p1.w;
        }
#pragma unroll
        for (int g = 0; g < 2; g++) {
            float4 A[4];
#pragma unroll
            for (int r = 0; r < 4; r++)
                A[r] = __ldcs(&hib[(w * 8 + g * 4 + r) * 64 + co + lane]);
#pragma unroll
            for (int r = 0; r < 4; r++) {
                const int n = w * 8 + g * 4 + r;
                float X[4] = {A[r].x, A[r].y, A[r].z, A[r].w};
                float acc[8];
#pragma unroll
                for (int h = 0; h < 8; h++) {
                    float s = 0.f;
#pragma unroll
                    for (int j = 0; j < 4; j++) s += X[j] * va[j][h];
                    acc[h] = s;
                }
#pragma unroll
                for (int st = 0; st < 3; st++) {
                    const int mask = 1 << st;
#pragma unroll
                    for (int p = 0; p < (4 >> st); p++) {
                        float aa = acc[2 * p], bb = acc[2 * p + 1];
                        float sel   = (lane & mask) ? aa : bb;
                        float other = __shfl_xor_sync(0xffffffffu, sel, mask);
                        acc[p] = (lane & mask) ? (bb + other) : (aa + other);
                    }
                }
                float rsum = acc[0];
                rsum += __shfl_xor_sync(0xffffffffu, rsum, 8);
                rsum += __shfl_xor_sync(0xffffffffu, rsum, 16);
                if (lane < 8) {
                    if (pass == 0) e_s[n * NH + lane] = rsum;
                    else           e_s[n * NH + lane] += rsum;
                }
            }
        }
    }

    // ---- 3. wait for hj tile ----
    mbar_wait(mb, 0);

    // ---- 4. hj half of logits from smem (single pass: va+vb both live) ----
    {
        float va[4][8], vb[4][8];
#pragma unroll
        for (int j = 0; j < 4; j++) {
            const int ia = 4 * lane + j;
            float4 p0 = vg[ia * 2], p1 = vg[ia * 2 + 1];
            va[j][0]=p0.x; va[j][1]=p0.y; va[j][2]=p0.z; va[j][3]=p0.w;
            va[j][4]=p1.x; va[j][5]=p1.y; va[j][6]=p1.z; va[j][7]=p1.w;
            const int ib = 128 + 4 * lane + j;
            float4 q0 = vg[ib * 2], q1 = vg[ib * 2 + 1];
            vb[j][0]=q0.x; vb[j][1]=q0.y; vb[j][2]=q0.z; vb[j][3]=q0.w;
            vb[j][4]=q1.x; vb[j][5]=q1.y; vb[j][6]=q1.z; vb[j][7]=q1.w;
        }
#pragma unroll
        for (int r = 0; r < 8; r++) {
            const int n = w * 8 + r;
            float4 b0 = hjs4[n * 64 + lane];
            float4 b1 = hjs4[n * 64 + 32 + lane];
            float acc[8];
#pragma unroll
            for (int h = 0; h < 8; h++) {
                float s = b0.x * va[0][h] + b0.y * va[1][h] + b0.z * va[2][h] + b0.w * va[3][h];
                s      += b1.x * vb[0][h] + b1.y * vb[1][h] + b1.z * vb[2][h] + b1.w * vb[3][h];
                acc[h] = s;
            }
#pragma unroll
            for (int st = 0; st < 3; st++) {
                const int mask = 1 << st;
#pragma unroll
                for (int p = 0; p < (4 >> st); p++) {
                    float aa = acc[2 * p], bb = acc[2 * p + 1];
                    float sel   = (lane & mask) ? aa : bb;
                    float other = __shfl_xor_sync(0xffffffffu, sel, mask);
                    acc[p] = (lane & mask) ? (bb + other) : (aa + other);
                }
            }
            float rsum = acc[0];
            rsum += __shfl_xor_sync(0xffffffffu, rsum, 8);
            rsum += __shfl_xor_sync(0xffffffffu, rsum, 16);
            if (lane < 8) e_s[n * NH + lane] += rsum;
        }
    }
    __syncthreads();

    // ---- 5. softmax over n (warp w = head w) ----
    {
        float e0 = e_s[lane * NH + w];
        float e1 = e_s[(lane + 32) * NH + w];
        e0 = (e0 >= 0.f) ? e0 : 0.2f * e0;   // leaky_relu(., 0.2)
        e1 = (e1 >= 0.f) ? e1 : 0.2f * e1;
        float m = fmaxf(e0, e1);
#pragma unroll
        for (int o = 16; o > 0; o >>= 1)
            m = fmaxf(m, __shfl_xor_sync(0xffffffffu, m, o));
        float p0 = __expf(e0 - m);
        float p1 = __expf(e1 - m);
        float sm = p0 + p1;
#pragma unroll
        for (int o = 16; o > 0; o >>= 1)
            sm += __shfl_xor_sync(0xffffffffu, sm, o);
        float inv = 1.f / sm;
        alpha_s[lane * NH + w]        = p0 * inv;
        alpha_s[(lane + 32) * NH + w] = p1 * inv;
    }
    __syncthreads();

    // ---- 6. phase 2: thread t owns in-index t (all from smem) ----
    float acc2[8] = {0.f, 0.f, 0.f, 0.f, 0.f, 0.f, 0.f, 0.f};
#pragma unroll 8
    for (int n = 0; n < N_NEIGH; n++) {
        float x = hj_s[n * IN_DIM + t];                                    // conflict-free
        float4 al0 = *reinterpret_cast<const float4*>(alpha_s + n * NH);   // broadcast
        float4 al1 = *reinterpret_cast<const float4*>(alpha_s + n * NH + 4);
        acc2[0] += al0.x * x; acc2[1] += al0.y * x;
        acc2[2] += al0.z * x; acc2[3] += al0.w * x;
        acc2[4] += al1.x * x; acc2[5] += al1.y * x;
        acc2[6] += al1.z * x; acc2[7] += al1.w * x;
    }
    float* sp = g_s + (size_t)b * NH * IN_DIM + t;
#pragma unroll
    for (int h = 0; h < 8; h++) sp[h * IN_DIM] = acc2[h];   // coalesced
}

// ---------------------------------------------------------------------------
// Stage 2: out[b][h*32+d] = elu( sum_in s[b][h][in] * W[in][h*32+d] )
// Grid: (B/32, NH) = 512 CTAs, 3 CTAs/SM.
// ---------------------------------------------------------------------------
#define S2_BL 32
#define S2_SMEM_FLOATS (IN_DIM * (S2_BL + 1) + IN_DIM * HD)
#define S2_SMEM_BYTES  (S2_SMEM_FLOATS * 4)

__global__ __launch_bounds__(256, 3)
void k_stage2(const float* __restrict__ W, float* __restrict__ out) {
    extern __shared__ __align__(16) float smem2[];
    float* s_sT = smem2;                            // [256][33]
    float* W_s  = smem2 + IN_DIM * (S2_BL + 1);     // [256][32]

    const int h    = blockIdx.y;
    const int b0   = blockIdx.x * S2_BL;
    const int t    = threadIdx.x;
    const int w    = t >> 5;
    const int lane = t & 31;

    {
        const float4* Wg4 = reinterpret_cast<const float4*>(W);
        float4 wbuf[8];
#pragma unroll
        for (int it = 0; it < 8; it++) {
            const int idx = it * 256 + t;
            wbuf[it] = __ldg(&Wg4[(idx >> 3) * 64 + h * 8 + (idx & 7)]);
        }
#pragma unroll
        for (int it = 0; it < 8; it++) {
            const int idx = it * 256 + t;
            *reinterpret_cast<float4*>(&W_s[(idx >> 3) * HD + (idx & 7) * 4]) = wbuf[it];
        }
    }
    {
        const float4* sg4 = reinterpret_cast<const float4*>(g_s);
        float4 sbuf[8];
#pragma unroll
        for (int it = 0; it < 8; it++) {
            const int idx = it * 256 + t;
            const int bl  = idx >> 6;
            const int inq = idx & 63;
            sbuf[it] = sg4[(((size_t)(b0 + bl)) * NH + h) * 64 + inq];
        }
#pragma unroll
        for (int it = 0; it < 8; it++) {
            const int idx = it * 256 + t;
            const int bl  = idx >> 6;
            const int inq = idx & 63;
            s_sT[(inq * 4 + 0) * (S2_BL + 1) + bl] = sbuf[it].x;
            s_sT[(inq * 4 + 1) * (S2_BL + 1) + bl] = sbuf[it].y;
            s_sT[(inq * 4 + 2) * (S2_BL + 1) + bl] = sbuf[it].z;
            s_sT[(inq * 4 + 3) * (S2_BL + 1) + bl] = sbuf[it].w;
        }
    }
    __syncthreads();

    const int bl = w * 4 + (lane >> 3);
    const int dq = lane & 7;

    float4 acc = {0.f, 0.f, 0.f, 0.f};
#pragma unroll 8
    for (int in = 0; in < IN_DIM; in++) {
        float  sv = s_sT[in * (S2_BL + 1) + bl];
        float4 w4 = *reinterpret_cast<const float4*>(&W_s[in * HD + dq * 4]);
        acc.x += sv * w4.x; acc.y += sv * w4.y; acc.z += sv * w4.z; acc.w += sv * w4.w;
    }

    float vals[4] = {acc.x, acc.y, acc.z, acc.w};
#pragma unroll
    for (int q = 0; q < 4; q++) {
        float x = vals[q];
        vals[q] = (x > 0.f) ? x : expm1f(x);   // elu
    }
    float* op = out + ((size_t)(b0 + bl)) * (NH * HD) + h * HD + dq * 4;
    *reinterpret_cast<float4*>(op) = make_float4(vals[0], vals[1], vals[2], vals[3]);
}

// ---------------------------------------------------------------------------
extern "C" void kernel_launch(void* const* d_in, const int* in_sizes, int n_in,
                              void* d_out, int out_size) {
    (void)in_sizes; (void)n_in; (void)out_size;
    const float* hi = (const float*)d_in[0];   // h_i_list [2048,64,256]
    const float* hj = (const float*)d_in[1];   // h_j_list [2048,64,256]
    const float* W  = (const float*)d_in[2];   // W [256,256]
    const float* Wa = (const float*)d_in[3];   // W_att [1,8,32]
    float* out = (float*)d_out;                // [2048,1,256]

    cudaFuncSetAttribute(k_stage1, cudaFuncAttributeMaxDynamicSharedMemorySize, S1_SMEM_BYTES);
    cudaFuncSetAttribute(k_stage2, cudaFuncAttributeMaxDynamicSharedMemorySize, S2_SMEM_BYTES);

    // 5 launches: slot #4 (ncu -s 5 -c 1) lands on k_stage1.
    k_compute_v<<<16, 64>>>(W, Wa, 0);
    k_compute_v<<<16, 64>>>(W, Wa, 1024);
    k_stage1<<<B_TOTAL / 2, 256, S1_SMEM_BYTES>>>(hi, hj, 0);
    k_stage1<<<B_TOTAL / 2, 256, S1_SMEM_BYTES>>>(hi, hj, B_TOTAL / 2);
    dim3 g2(B_TOTAL / S2_BL, NH);
    k_stage2<<<g2, 256, S2_SMEM_BYTES>>>(W, out);
}

// round 11
// speedup vs baseline: 1.7137x; 1.7137x over previous
#include <cuda_runtime.h>
#include <math.h>

#define B_TOTAL  2048
#define N_NEIGH  64
#define IN_DIM   256
#define NH       8
#define HD       32

// Scratch (allocation-free rule: __device__ globals)
__device__ float g_v[IN_DIM * NH];                         // v[in][h]
__device__ float g_s[(size_t)B_TOTAL * NH * IN_DIM];       // s[b][h][in]

// Streaming load: no L1 allocation (no fill wavefronts through l1tex).
__device__ __forceinline__ float4 ldg_na(const float4* p) {
    float4 v;
    asm volatile("ld.global.nc.L1::no_allocate.v4.f32 {%0,%1,%2,%3}, [%4];"
                 : "=f"(v.x), "=f"(v.y), "=f"(v.z), "=f"(v.w) : "l"(p));
    return v;
}

// ---------------------------------------------------------------------------
// Kernel 0: v[in][h] = sum_d W[in][h*32+d] * W_att[h][d]
// ---------------------------------------------------------------------------
__global__ __launch_bounds__(64, 8)
void k_compute_v(const float* __restrict__ W, const float* __restrict__ Wa, int base) {
    const int idx = base + blockIdx.x * 64 + threadIdx.x;
    const int in  = idx >> 3;
    const int h   = idx & 7;
    const float4* row = reinterpret_cast<const float4*>(W + (size_t)in * (NH * HD) + h * HD);
    const float4* wa4 = reinterpret_cast<const float4*>(Wa) + h * 8;
    float4 w[8];
#pragma unroll
    for (int q = 0; q < 8; q++) w[q] = row[q];
    float acc = 0.f;
#pragma unroll
    for (int q = 0; q < 8; q++) {
        float4 a4 = __ldg(&wa4[q]);
        acc += w[q].x * a4.x + w[q].y * a4.y + w[q].z * a4.z + w[q].w * a4.w;
    }
    g_v[in * NH + h] = acc;
}

// ---------------------------------------------------------------------------
// Stage 1 (R4 structure, streams via L1::no_allocate):
//   e[n][h]   = leaky( (hi[n]+hj[n]) . v[:,h] )
//   alpha     = softmax_n(e)
//   s[h][in]  = sum_n alpha[n][h] * hj[n][in]   -> g_s
// Two-pass in-split (32 v-regs). 4-row load groups (32 buffer regs). occ 2.
// Dynamic smem (floats): hj_s[64][256]; e_s[64][8]; alpha_s[64][8]
// ---------------------------------------------------------------------------
#define S1_SMEM_FLOATS (16384 + 512 + 512)
#define S1_SMEM_BYTES  (S1_SMEM_FLOATS * 4)

__global__ __launch_bounds__(256, 2)
void k_stage1(const float* __restrict__ hi, const float* __restrict__ hj, int b_base) {
    extern __shared__ __align__(16) float smem[];
    float* hj_s    = smem;            // [64][256]
    float* e_s     = smem + 16384;    // [64][8]
    float* alpha_s = smem + 16896;    // [64][8]

    const int b    = b_base + blockIdx.x;
    const int t    = threadIdx.x;
    const int w    = t >> 5;
    const int lane = t & 31;

    const float4* hib = reinterpret_cast<const float4*>(hi + (size_t)b * N_NEIGH * IN_DIM);
    const float4* hjb = reinterpret_cast<const float4*>(hj + (size_t)b * N_NEIGH * IN_DIM);
    const float4* vg  = reinterpret_cast<const float4*>(g_v);

#pragma unroll
    for (int pass = 0; pass < 2; pass++) {
        const int co = pass * 32;     // float4 column offset within a row

        // v for this lane's fixed in-set: in = 128*pass + 4*lane + j
        float va[4][8];
#pragma unroll
        for (int j = 0; j < 4; j++) {
            const int ia = 128 * pass + 4 * lane + j;
            float4 p0 = vg[ia * 2], p1 = vg[ia * 2 + 1];
            va[j][0]=p0.x; va[j][1]=p0.y; va[j][2]=p0.z; va[j][3]=p0.w;
            va[j][4]=p1.x; va[j][5]=p1.y; va[j][6]=p1.z; va[j][7]=p1.w;
        }

#pragma unroll
        for (int g = 0; g < 2; g++) {
            // ---- front-batched streaming loads: 8 LDG.128, no L1 allocation ----
            float4 A[4], Bv[4];
#pragma unroll
            for (int r = 0; r < 4; r++)
                A[r]  = ldg_na(&hib[(w * 8 + g * 4 + r) * 64 + co + lane]);
#pragma unroll
            for (int r = 0; r < 4; r++)
                Bv[r] = ldg_na(&hjb[(w * 8 + g * 4 + r) * 64 + co + lane]);

            float X[4][4];
#pragma unroll
            for (int r = 0; r < 4; r++) {
                X[r][0] = A[r].x + Bv[r].x; X[r][1] = A[r].y + Bv[r].y;
                X[r][2] = A[r].z + Bv[r].z; X[r][3] = A[r].w + Bv[r].w;
                reinterpret_cast<float4*>(hj_s + (w * 8 + g * 4 + r) * IN_DIM)[co + lane] = Bv[r];
            }

#pragma unroll
            for (int r = 0; r < 4; r++) {
                const int n = w * 8 + g * 4 + r;
                float acc[8];
#pragma unroll
                for (int h = 0; h < 8; h++) {
                    float s = 0.f;
#pragma unroll
                    for (int j = 0; j < 4; j++) s += X[r][j] * va[j][h];
                    acc[h] = s;
                }
                // Fold 8 head-accumulators into lane dim, then 8/16 fold.
#pragma unroll
                for (int st = 0; st < 3; st++) {
                    const int mask = 1 << st;
#pragma unroll
                    for (int p = 0; p < (4 >> st); p++) {
                        float aa = acc[2 * p], bb = acc[2 * p + 1];
                        float sel   = (lane & mask) ? aa : bb;
                        float other = __shfl_xor_sync(0xffffffffu, sel, mask);
                        acc[p] = (lane & mask) ? (bb + other) : (aa + other);
                    }
                }
                float rsum = acc[0];
                rsum += __shfl_xor_sync(0xffffffffu, rsum, 8);
                rsum += __shfl_xor_sync(0xffffffffu, rsum, 16);
                if (lane < 8) {
                    if (pass == 0) e_s[n * NH + lane] = rsum;
                    else           e_s[n * NH + lane] += rsum;
                }
            }
        }
    }
    __syncthreads();

    // ---- Softmax over n (warp w = head w) ----
    {
        float e0 = e_s[lane * NH + w];
        float e1 = e_s[(lane + 32) * NH + w];
        e0 = (e0 >= 0.f) ? e0 : 0.2f * e0;   // leaky_relu(., 0.2)
        e1 = (e1 >= 0.f) ? e1 : 0.2f * e1;
        float m = fmaxf(e0, e1);
#pragma unroll
        for (int o = 16; o > 0; o >>= 1)
            m = fmaxf(m, __shfl_xor_sync(0xffffffffu, m, o));
        float p0 = __expf(e0 - m);
        float p1 = __expf(e1 - m);
        float sm = p0 + p1;
#pragma unroll
        for (int o = 16; o > 0; o >>= 1)
            sm += __shfl_xor_sync(0xffffffffu, sm, o);
        float inv = 1.f / sm;
        alpha_s[lane * NH + w]        = p0 * inv;
        alpha_s[(lane + 32) * NH + w] = p1 * inv;
    }
    __syncthreads();

    // ---- Phase 2: thread t owns in-index t; s[h][t] = sum_n alpha[n][h]*hj[n][t] ----
    float acc2[8] = {0.f, 0.f, 0.f, 0.f, 0.f, 0.f, 0.f, 0.f};
#pragma unroll 8
    for (int n = 0; n < N_NEIGH; n++) {
        float x = hj_s[n * IN_DIM + t];                                    // conflict-free
        float4 al0 = *reinterpret_cast<const float4*>(alpha_s + n * NH);   // broadcast
        float4 al1 = *reinterpret_cast<const float4*>(alpha_s + n * NH + 4);
        acc2[0] += al0.x * x; acc2[1] += al0.y * x;
        acc2[2] += al0.z * x; acc2[3] += al0.w * x;
        acc2[4] += al1.x * x; acc2[5] += al1.y * x;
        acc2[6] += al1.z * x; acc2[7] += al1.w * x;
    }
    float* sp = g_s + (size_t)b * NH * IN_DIM + t;
#pragma unroll
    for (int h = 0; h < 8; h++) sp[h * IN_DIM] = acc2[h];   // coalesced
}

// ---------------------------------------------------------------------------
// Stage 2 (R4 version): out[b][h*32+d] = elu( sum_in s[b][h][in]*W[in][h*32+d] )
// Grid: (B/64, NH) = 256 CTAs, float4 + fully unrolled smem fills.
// Dynamic smem (floats): s_sT[256][65]; W_s[256][32]
// ---------------------------------------------------------------------------
#define S2_BL 64
#define S2_SMEM_FLOATS (IN_DIM * (S2_BL + 1) + IN_DIM * HD)
#define S2_SMEM_BYTES  (S2_SMEM_FLOATS * 4)

__global__ __launch_bounds__(256, 2)
void k_stage2(const float* __restrict__ W, float* __restrict__ out) {
    extern __shared__ __align__(16) float smem2[];
    float* s_sT = smem2;                            // [256][65]
    float* W_s  = smem2 + IN_DIM * (S2_BL + 1);     // [256][32]

    const int h    = blockIdx.y;
    const int b0   = blockIdx.x * S2_BL;
    const int t    = threadIdx.x;
    const int w    = t >> 5;
    const int lane = t & 31;

    {
        const float4* Wg4 = reinterpret_cast<const float4*>(W);
        float4 wbuf[8];
#pragma unroll
        for (int it = 0; it < 8; it++) {
            const int idx = it * 256 + t;
            wbuf[it] = __ldg(&Wg4[(idx >> 3) * 64 + h * 8 + (idx & 7)]);
        }
#pragma unroll
        for (int it = 0; it < 8; it++) {
            const int idx = it * 256 + t;
            *reinterpret_cast<float4*>(&W_s[(idx >> 3) * HD + (idx & 7) * 4]) = wbuf[it];
        }
    }
    {
        const float4* sg4 = reinterpret_cast<const float4*>(g_s);
#pragma unroll
        for (int half = 0; half < 2; half++) {
            float4 sbuf[8];
#pragma unroll
            for (int it = 0; it < 8; it++) {
                const int idx = (half * 8 + it) * 256 + t;
                const int bl  = idx >> 6;
                const int inq = idx & 63;
                sbuf[it] = sg4[(((size_t)(b0 + bl)) * NH + h) * 64 + inq];
            }
#pragma unroll
            for (int it = 0; it < 8; it++) {
                const int idx = (half * 8 + it) * 256 + t;
                const int bl  = idx >> 6;
                const int inq = idx & 63;
                s_sT[(inq * 4 + 0) * (S2_BL + 1) + bl] = sbuf[it].x;
                s_sT[(inq * 4 + 1) * (S2_BL + 1) + bl] = sbuf[it].y;
                s_sT[(inq * 4 + 2) * (S2_BL + 1) + bl] = sbuf[it].z;
                s_sT[(inq * 4 + 3) * (S2_BL + 1) + bl] = sbuf[it].w;
            }
        }
    }
    __syncthreads();

    const int bh = w & 1;
    const int dq = w >> 1;
    const int bl = bh * 32 + lane;

    float4 acc0 = {0,0,0,0}, acc1 = {0,0,0,0};
#pragma unroll 8
    for (int in = 0; in < IN_DIM; in++) {
        float  sv = s_sT[in * (S2_BL + 1) + bl];
        float4 w0 = *reinterpret_cast<const float4*>(&W_s[in * HD + dq * 8]);
        float4 w1 = *reinterpret_cast<const float4*>(&W_s[in * HD + dq * 8 + 4]);
        acc0.x += sv * w0.x; acc0.y += sv * w0.y; acc0.z += sv * w0.z; acc0.w += sv * w0.w;
        acc1.x += sv * w1.x; acc1.y += sv * w1.y; acc1.z += sv * w1.z; acc1.w += sv * w1.w;
    }

    float vals[8] = {acc0.x, acc0.y, acc0.z, acc0.w, acc1.x, acc1.y, acc1.z, acc1.w};
#pragma unroll
    for (int q = 0; q < 8; q++) {
        float x = vals[q];
        vals[q] = (x > 0.f) ? x : expm1f(x);   // elu
    }
    float* op = out + ((size_t)(b0 + bl)) * (NH * HD) + h * HD + dq * 8;
    *reinterpret_cast<float4*>(op)     = make_float4(vals[0], vals[1], vals[2], vals[3]);
    *reinterpret_cast<float4*>(op + 4) = make_float4(vals[4], vals[5], vals[6], vals[7]);
}

// ---------------------------------------------------------------------------
extern "C" void kernel_launch(void* const* d_in, const int* in_sizes, int n_in,
                              void* d_out, int out_size) {
    (void)in_sizes; (void)n_in; (void)out_size;
    const float* hi = (const float*)d_in[0];   // h_i_list [2048,64,256]
    const float* hj = (const float*)d_in[1];   // h_j_list [2048,64,256]
    const float* W  = (const float*)d_in[2];   // W [256,256]
    const float* Wa = (const float*)d_in[3];   // W_att [1,8,32]
    float* out = (float*)d_out;                // [2048,1,256]

    cudaFuncSetAttribute(k_stage1, cudaFuncAttributeMaxDynamicSharedMemorySize, S1_SMEM_BYTES);
    cudaFuncSetAttribute(k_stage2, cudaFuncAttributeMaxDynamicSharedMemorySize, S2_SMEM_BYTES);

    // 5 launches: ncu (-s 5 -c 1) lands on k_stage1 (slot #4).
    k_compute_v<<<16, 64>>>(W, Wa, 0);
    k_compute_v<<<16, 64>>>(W, Wa, 1024);
    k_stage1<<<B_TOTAL / 2, 256, S1_SMEM_BYTES>>>(hi, hj, 0);
    k_stage1<<<B_TOTAL / 2, 256, S1_SMEM_BYTES>>>(hi, hj, B_TOTAL / 2);
    dim3 g2(B_TOTAL / S2_BL, NH);
    k_stage2<<<g2, 256, S2_SMEM_BYTES>>>(W, out);
}